// round 1
// baseline (speedup 1.0000x reference)
#include <cuda_runtime.h>

#define C 128          // channels
#define G 1024         // num graphs / segments
#define S 32           // squeeze dim
#define SEG_RPW 128    // rows per warp in segment-sum kernel
#define SCL_RPW 4      // rows per warp in scale kernel

// Scratch (device globals: no allocation allowed)
__device__ float g_sums[G * C];
__device__ float g_counts[G];
__device__ float g_excite[G * C];
__device__ int   g_is32;

// ---------------------------------------------------------------------------
// Detect whether batch is int32 or int64.
// Values are in [0, 1024). If stored as int64 (little-endian), every odd
// 4-byte word is 0 and word index (N-1) [odd for N=2^20] is a high word = 0.
// If stored as int32, word (N-1) = batch[N-1] ~= 1023 != 0.
// Reading word (N-1) is in-bounds for both layouts (4(N-1) < 4N <= 8N).
// ---------------------------------------------------------------------------
__global__ void detect_kernel(const int* __restrict__ bw, int N) {
    g_is32 = (bw[N - 1] != 0) ? 1 : 0;
}

__global__ void zero_kernel() {
    int i = blockIdx.x * blockDim.x + threadIdx.x;
    if (i < G * C) g_sums[i] = 0.f;
    if (i < G)     g_counts[i] = 0.f;
}

__device__ __forceinline__ int load_batch(const void* batch, long long r, int is32) {
    if (is32) return ((const int*)batch)[r];
    return (int)((const long long*)batch)[r];
}

// ---------------------------------------------------------------------------
// Segment sum: one warp owns SEG_RPW consecutive rows. Lane l accumulates
// channels [4l, 4l+4) in a float4 register; flush to global atomics only when
// the (sorted) segment id changes or at chunk end.
// ---------------------------------------------------------------------------
__global__ void seg_kernel(const float4* __restrict__ x4,
                           const void*   __restrict__ batch,
                           int N) {
    int warp = (blockIdx.x * blockDim.x + threadIdx.x) >> 5;
    int lane = threadIdx.x & 31;
    long long r0 = (long long)warp * SEG_RPW;
    if (r0 >= N) return;
    long long r1 = r0 + SEG_RPW;
    if (r1 > N) r1 = N;

    const int is32 = g_is32;

    float4 acc = make_float4(0.f, 0.f, 0.f, 0.f);
    float  cnt = 0.f;
    int    cur = -1;

    for (long long r = r0; r < r1; ++r) {
        int g = 0;
        if (lane == 0) g = load_batch(batch, r, is32);
        g = __shfl_sync(0xffffffffu, g, 0);

        if (g != cur) {
            if (cur >= 0) {
                float* dst = &g_sums[(long long)cur * C + lane * 4];
                atomicAdd(dst + 0, acc.x);
                atomicAdd(dst + 1, acc.y);
                atomicAdd(dst + 2, acc.z);
                atomicAdd(dst + 3, acc.w);
                if (lane == 0) atomicAdd(&g_counts[cur], cnt);
            }
            cur = g;
            acc = make_float4(0.f, 0.f, 0.f, 0.f);
            cnt = 0.f;
        }

        float4 v = x4[r * 32 + lane];
        acc.x += v.x; acc.y += v.y; acc.z += v.z; acc.w += v.w;
        cnt += 1.f;
    }

    if (cur >= 0) {
        float* dst = &g_sums[(long long)cur * C + lane * 4];
        atomicAdd(dst + 0, acc.x);
        atomicAdd(dst + 1, acc.y);
        atomicAdd(dst + 2, acc.z);
        atomicAdd(dst + 3, acc.w);
        if (lane == 0) atomicAdd(&g_counts[cur], cnt);
    }
}

// ---------------------------------------------------------------------------
// Gate: one block (128 threads) per graph.
//   mean = sums / max(count,1)
//   s    = relu(mean @ W_s^T + b_s)        [32]
//   e    = sigmoid(s @ W_e^T + b_e)        [128]
// ---------------------------------------------------------------------------
__global__ void gate_kernel(const float* __restrict__ Ws,
                            const float* __restrict__ bs,
                            const float* __restrict__ We,
                            const float* __restrict__ be) {
    __shared__ float mean[C];
    __shared__ float sq[S];
    int g = blockIdx.x;
    int t = threadIdx.x;

    float cntv = g_counts[g];
    mean[t] = g_sums[g * C + t] / fmaxf(cntv, 1.f);
    __syncthreads();

    if (t < S) {
        float acc = bs[t];
        const float* w = Ws + t * C;
        #pragma unroll 8
        for (int c = 0; c < C; ++c) acc += mean[c] * w[c];
        sq[t] = fmaxf(acc, 0.f);
    }
    __syncthreads();

    float e = be[t];
    const float* w = We + t * S;
    #pragma unroll
    for (int j = 0; j < S; ++j) e += sq[j] * w[j];
    g_excite[g * C + t] = 1.f / (1.f + __expf(-e));
}

// ---------------------------------------------------------------------------
// Scale: one warp handles SCL_RPW rows; lane l does float4 channel slice l.
// excite rows (512 B each, 512 KB total) stay resident in L2.
// ---------------------------------------------------------------------------
__global__ void scale_kernel(const float4* __restrict__ x4,
                             const void*   __restrict__ batch,
                             float4*       __restrict__ out4,
                             int N) {
    int warp = (blockIdx.x * blockDim.x + threadIdx.x) >> 5;
    int lane = threadIdx.x & 31;
    long long r0 = (long long)warp * SCL_RPW;
    if (r0 >= N) return;
    long long r1 = r0 + SCL_RPW;
    if (r1 > N) r1 = N;

    const int is32 = g_is32;

    for (long long r = r0; r < r1; ++r) {
        int g = 0;
        if (lane == 0) g = load_batch(batch, r, is32);
        g = __shfl_sync(0xffffffffu, g, 0);

        const float4* erow = (const float4*)(g_excite + (long long)g * C);
        float4 e = erow[lane];
        float4 v = x4[r * 32 + lane];
        float4 o;
        o.x = v.x * e.x; o.y = v.y * e.y; o.z = v.z * e.z; o.w = v.w * e.w;
        out4[r * 32 + lane] = o;
    }
}

extern "C" void kernel_launch(void* const* d_in, const int* in_sizes, int n_in,
                              void* d_out, int out_size) {
    const float* x     = (const float*)d_in[0];
    const void*  batch = d_in[1];
    const float* Ws    = (const float*)d_in[2];
    const float* bs    = (const float*)d_in[3];
    const float* We    = (const float*)d_in[4];
    const float* be    = (const float*)d_in[5];
    float*       out   = (float*)d_out;

    int N = in_sizes[0] / C;   // number of nodes

    detect_kernel<<<1, 1>>>((const int*)batch, N);
    zero_kernel<<<(G * C + 255) / 256, 256>>>();

    {   // segment sums
        long long warps = ((long long)N + SEG_RPW - 1) / SEG_RPW;
        int blocks = (int)((warps * 32 + 255) / 256);
        seg_kernel<<<blocks, 256>>>((const float4*)x, batch, N);
    }

    gate_kernel<<<G, C>>>(Ws, bs, We, be);

    {   // scale
        long long warps = ((long long)N + SCL_RPW - 1) / SCL_RPW;
        int blocks = (int)((warps * 32 + 255) / 256);
        scale_kernel<<<blocks, 256>>>((const float4*)x, batch, (float4*)out, N);
    }
}

// round 2
// speedup vs baseline: 1.1144x; 1.1144x over previous
#include <cuda_runtime.h>

#define C 128          // channels
#define G 1024         // num graphs / segments
#define S 32           // squeeze dim
#define SEG_RPW 128    // rows per warp in segment-sum kernel
#define SCL_RPW 8      // rows per warp in scale kernel
#define GPB 8          // graphs per block in gate kernel

// Scratch (device globals: no allocation allowed)
__device__ float g_sums[G * C];
__device__ float g_counts[G];
__device__ float g_excite[G * C];
__device__ int   g_is32;

// ---------------------------------------------------------------------------
// Detect whether batch is int32 or int64.
// Values are in [0, 1024). If int64 (LE), word (N-1) [odd] is a high word = 0.
// If int32, word (N-1) = batch[N-1] ~ 1023 != 0. In-bounds for both layouts.
// ---------------------------------------------------------------------------
__global__ void detect_kernel(const int* __restrict__ bw, int N) {
    g_is32 = (bw[N - 1] != 0) ? 1 : 0;
}

__global__ void zero_kernel() {
    int i = blockIdx.x * blockDim.x + threadIdx.x;
    if (i < G * C) g_sums[i] = 0.f;
    if (i < G)     g_counts[i] = 0.f;
}

// Load batch[r] as int32: for int64 input read only the low 32-bit word.
__device__ __forceinline__ int load_batch32(const int* __restrict__ bw,
                                            long long r, int is32) {
    return bw[is32 ? r : 2 * r];
}

// ---------------------------------------------------------------------------
// Segment sum: warp owns SEG_RPW consecutive rows. Batch ids are front-loaded
// 32 rows at a time (one coalesced lane load), then broadcast via shfl so the
// global-load latency is off the per-row critical path. Lane l accumulates
// channels [4l,4l+4) in registers; flush to atomics only on segment change.
// ---------------------------------------------------------------------------
__global__ void seg_kernel(const float4* __restrict__ x4,
                           const int*    __restrict__ bw,
                           int N) {
    int warp = (blockIdx.x * blockDim.x + threadIdx.x) >> 5;
    int lane = threadIdx.x & 31;
    long long r0 = (long long)warp * SEG_RPW;
    if (r0 >= N) return;
    long long r1 = r0 + SEG_RPW;
    if (r1 > N) r1 = N;

    const int is32 = g_is32;

    float4 acc = make_float4(0.f, 0.f, 0.f, 0.f);
    float  cnt = 0.f;
    int    cur = -1;

    for (long long base = r0; base < r1; base += 32) {
        int rows = (int)((r1 - base < 32) ? (r1 - base) : 32);
        int bv = 0;
        if (lane < rows) bv = load_batch32(bw, base + lane, is32);

        for (int k = 0; k < rows; ++k) {
            int g = __shfl_sync(0xffffffffu, bv, k);
            if (g != cur) {
                if (cur >= 0) {
                    float* dst = &g_sums[(long long)cur * C + lane * 4];
                    atomicAdd(dst + 0, acc.x);
                    atomicAdd(dst + 1, acc.y);
                    atomicAdd(dst + 2, acc.z);
                    atomicAdd(dst + 3, acc.w);
                    if (lane == 0) atomicAdd(&g_counts[cur], cnt);
                }
                cur = g;
                acc = make_float4(0.f, 0.f, 0.f, 0.f);
                cnt = 0.f;
            }
            float4 v = __ldcs(&x4[(base + k) * 32 + lane]);
            acc.x += v.x; acc.y += v.y; acc.z += v.z; acc.w += v.w;
            cnt += 1.f;
        }
    }

    if (cur >= 0) {
        float* dst = &g_sums[(long long)cur * C + lane * 4];
        atomicAdd(dst + 0, acc.x);
        atomicAdd(dst + 1, acc.y);
        atomicAdd(dst + 2, acc.z);
        atomicAdd(dst + 3, acc.w);
        if (lane == 0) atomicAdd(&g_counts[cur], cnt);
    }
}

// ---------------------------------------------------------------------------
// Gate: 256-thread block handles GPB=8 graphs, one warp per graph.
// Ws is staged in shared with stride 129 (lane j reads WsS[j*129+c]: bank =
// (j*129+c)%32 = (j+c)%32 -> conflict-free across lanes at fixed c).
// We staged with stride 33 for the same reason in stage 2.
// ---------------------------------------------------------------------------
__global__ void gate_kernel(const float* __restrict__ Ws,
                            const float* __restrict__ bs,
                            const float* __restrict__ We,
                            const float* __restrict__ be) {
    __shared__ float WsS[S * 129];       // WsS[j*129 + c]
    __shared__ float WeS[C * 33];        // WeS[t*33 + j]
    __shared__ float meanS[GPB][C];
    __shared__ float sqS[GPB][S];

    int t = threadIdx.x;
    for (int i = t; i < S * C; i += 256) {
        int j = i >> 7, c = i & 127;
        WsS[j * 129 + c] = Ws[i];
    }
    for (int i = t; i < C * S; i += 256) {
        int r = i >> 5, j = i & 31;
        WeS[r * 33 + j] = We[i];
    }

    int warp = t >> 5, lane = t & 31;
    int g = blockIdx.x * GPB + warp;

    // mean = sums / max(count,1)
    float4 s4  = ((const float4*)(g_sums + (long long)g * C))[lane];
    float  inv = 1.f / fmaxf(g_counts[g], 1.f);
    meanS[warp][lane * 4 + 0] = s4.x * inv;
    meanS[warp][lane * 4 + 1] = s4.y * inv;
    meanS[warp][lane * 4 + 2] = s4.z * inv;
    meanS[warp][lane * 4 + 3] = s4.w * inv;
    __syncthreads();   // covers WsS/WeS staging (meanS is same-warp)

    // stage 1: lane j computes sq[j]
    float acc = bs[lane];
    #pragma unroll
    for (int c = 0; c < C; ++c)
        acc += meanS[warp][c] * WsS[lane * 129 + c];   // meanS: broadcast
    sqS[warp][lane] = fmaxf(acc, 0.f);
    __syncwarp();

    // stage 2: lane computes outputs t4 = 4*lane .. 4*lane+3
    float4 bv = ((const float4*)be)[lane];
    float e0 = bv.x, e1 = bv.y, e2 = bv.z, e3 = bv.w;
    int tb = lane * 4;
    #pragma unroll
    for (int j = 0; j < S; ++j) {
        float sv = sqS[warp][j];                        // broadcast
        e0 += sv * WeS[(tb + 0) * 33 + j];
        e1 += sv * WeS[(tb + 1) * 33 + j];
        e2 += sv * WeS[(tb + 2) * 33 + j];
        e3 += sv * WeS[(tb + 3) * 33 + j];
    }
    float4 o;
    o.x = 1.f / (1.f + __expf(-e0));
    o.y = 1.f / (1.f + __expf(-e1));
    o.z = 1.f / (1.f + __expf(-e2));
    o.w = 1.f / (1.f + __expf(-e3));
    ((float4*)(g_excite + (long long)g * C))[lane] = o;
}

// ---------------------------------------------------------------------------
// Scale: warp handles SCL_RPW rows; batch front-loaded (lane r reads row r's
// id), excite rows stay L2-resident, x streamed with .cs, out stored .cs.
// ---------------------------------------------------------------------------
__global__ void scale_kernel(const float4* __restrict__ x4,
                             const int*    __restrict__ bw,
                             float4*       __restrict__ out4,
                             int N) {
    int warp = (blockIdx.x * blockDim.x + threadIdx.x) >> 5;
    int lane = threadIdx.x & 31;
    long long r0 = (long long)warp * SCL_RPW;
    if (r0 >= N) return;
    int rows = (int)(((long long)N - r0 < SCL_RPW) ? ((long long)N - r0) : SCL_RPW);

    const int is32 = g_is32;

    int bv = 0;
    if (lane < rows) bv = load_batch32(bw, r0 + lane, is32);

    #pragma unroll
    for (int k = 0; k < SCL_RPW; ++k) {
        if (k >= rows) break;
        int g = __shfl_sync(0xffffffffu, bv, k);
        float4 e = ((const float4*)(g_excite + (long long)g * C))[lane];
        float4 v = __ldcs(&x4[(r0 + k) * 32 + lane]);
        float4 o;
        o.x = v.x * e.x; o.y = v.y * e.y; o.z = v.z * e.z; o.w = v.w * e.w;
        __stcs(&out4[(r0 + k) * 32 + lane], o);
    }
}

extern "C" void kernel_launch(void* const* d_in, const int* in_sizes, int n_in,
                              void* d_out, int out_size) {
    const float* x     = (const float*)d_in[0];
    const int*   batch = (const int*)d_in[1];
    const float* Ws    = (const float*)d_in[2];
    const float* bs    = (const float*)d_in[3];
    const float* We    = (const float*)d_in[4];
    const float* be    = (const float*)d_in[5];
    float*       out   = (float*)d_out;

    int N = in_sizes[0] / C;   // number of nodes

    detect_kernel<<<1, 1>>>(batch, N);
    zero_kernel<<<(G * C + 255) / 256, 256>>>();

    {   // segment sums
        long long warps = ((long long)N + SEG_RPW - 1) / SEG_RPW;
        int blocks = (int)((warps * 32 + 255) / 256);
        seg_kernel<<<blocks, 256>>>((const float4*)x, batch, N);
    }

    gate_kernel<<<G / GPB, 256>>>(Ws, bs, We, be);

    {   // scale
        long long warps = ((long long)N + SCL_RPW - 1) / SCL_RPW;
        int blocks = (int)((warps * 32 + 255) / 256);
        scale_kernel<<<blocks, 256>>>((const float4*)x, batch, (float4*)out, N);
    }
}